// round 15
// baseline (speedup 1.0000x reference)
#include <cuda_runtime.h>
#include <cstdint>

// Problem constants (fixed shapes from reference)
#define NUM_CLASSES 16
#define C_IN 21
#define D_HID 12      // 2*NUM_PARTS
#define P_OUT 7       // NUM_PARTS+1
#define BS 4
#define V 8
#define N_IMG (BS*V)  // 32
#define H 128
#define W 128
#define HW (H*W)      // 16384
#define EPS 1e-5f

#define PIX_PER_THREAD 4
#define THREADS 128
#define PIX_PER_BLOCK (THREADS * PIX_PER_THREAD)        // 512
#define BLOCKS_PER_IMG (HW / PIX_PER_BLOCK)             // 32
#define GRID (N_IMG * BLOCKS_PER_IMG)                   // 1024

// Output layout: tuple (out, feats) flattened:
//   out:   (32, 7, 128, 128)  at offset 0
//   feats: (32, 21, 128, 128) after it
#define OUT_ELEMS ((size_t)N_IMG * P_OUT * HW)

typedef unsigned long long u64;

// ---- packed f32x2 helpers (Blackwell FFMA2; ptxas never auto-fuses) ----
__device__ __forceinline__ u64 pack2(float a, float b) {
    u64 r;
    asm("mov.b64 %0, {%1, %2};" : "=l"(r) : "f"(a), "f"(b));
    return r;
}
__device__ __forceinline__ void unpack2(u64 v, float& a, float& b) {
    asm("mov.b64 {%0, %1}, %2;" : "=f"(a), "=f"(b) : "l"(v));
}
__device__ __forceinline__ u64 fma2(u64 a, u64 b, u64 c) {
    u64 d;
    asm("fma.rn.f32x2 %0, %1, %2, %3;" : "=l"(d) : "l"(a), "l"(b), "l"(c));
    return d;
}

__global__ __launch_bounds__(THREADS, 6)   // 85-reg ceiling: no spills, LDG pipelining room
void mvpartseg_fused_kernel(const float* __restrict__ x,     // (32,21,128,128)
                            const int*   __restrict__ cls,   // (4,1)
                            const float* __restrict__ W1,    // (16,12,21)
                            const float* __restrict__ b1,    // (16,12)
                            const float* __restrict__ g1,    // (16,12)
                            const float* __restrict__ be1,   // (16,12)
                            const float* __restrict__ rm1,   // (16,12)
                            const float* __restrict__ rv1,   // (16,12)
                            const float* __restrict__ W2,    // (16,7,12)
                            const float* __restrict__ b2,    // (16,7)
                            float* __restrict__ out)
{
    // Layer-1 weights transposed to [c][d]: 12 contiguous floats per channel
    // -> 3x LDS.128 per channel, broadcast (conflict-free). Plain fp32 in smem;
    // {w,w} duplication for f32x2 happens in registers (1 mov per weight-use).
    __shared__ __align__(16) float sA1t[C_IN * D_HID];   // 252, BN-folded
    __shared__ __align__(16) float sA2[P_OUT * D_HID];   // 84, [p][d]
    __shared__ float sc1[D_HID];                         // BN-folded bias
    __shared__ float sb2[P_OUT];
    __shared__ float sinv[D_HID];

    const int t = threadIdx.x;
    const int n = blockIdx.x / BLOCKS_PER_IMG;       // image (view-folded) index
    const int k = cls[n / V];                        // selected class head

    // Fold BN into conv1 params
    if (t < D_HID) {
        const int i = k * D_HID + t;
        float inv = g1[i] * rsqrtf(rv1[i] + EPS);
        sinv[t] = inv;
        sc1[t]  = b1[i] * inv + be1[i] - rm1[i] * inv;
    }
    if (t < P_OUT) sb2[t] = b2[k * P_OUT + t];
    __syncthreads();

    for (int i = t; i < C_IN * D_HID; i += THREADS) {
        int c = i / D_HID, d = i % D_HID;
        sA1t[i] = W1[k * D_HID * C_IN + d * C_IN + c] * sinv[d];
    }
    for (int i = t; i < P_OUT * D_HID; i += THREADS) {
        sA2[i] = W2[k * P_OUT * D_HID + i];
    }
    __syncthreads();

    const int pix = (blockIdx.x % BLOCKS_PER_IMG) * PIX_PER_BLOCK + t * PIX_PER_THREAD;
    const float* xin  = x + (size_t)n * C_IN * HW + pix;
    float*       fout = out + OUT_ELEMS + (size_t)n * C_IN * HW + pix;

    // Layer-1 accumulators: 4 pixels = 2 packed f32x2 lanes per hidden unit
    u64 acc01[D_HID], acc23[D_HID];
#pragma unroll
    for (int d = 0; d < D_HID; d++) {
        u64 bp = pack2(sc1[d], sc1[d]);
        acc01[d] = bp;
        acc23[d] = bp;
    }

    // Stream channels: LDG.128, streaming copy to feats, packed FFMA2 into accs.
#pragma unroll
    for (int c = 0; c < C_IN; c++) {
        const float4 xv = *(const float4*)(xin + (size_t)c * HW);
        __stcs((float4*)(fout + (size_t)c * HW), xv);
        const u64 x01 = pack2(xv.x, xv.y);
        const u64 x23 = pack2(xv.z, xv.w);
        const float4* wrow = (const float4*)&sA1t[c * D_HID];
#pragma unroll
        for (int q = 0; q < D_HID / 4; q++) {
            const float4 w = wrow[q];
            const u64 w0 = pack2(w.x, w.x);
            const u64 w1 = pack2(w.y, w.y);
            const u64 w2 = pack2(w.z, w.z);
            const u64 w3 = pack2(w.w, w.w);
            acc01[4*q+0] = fma2(w0, x01, acc01[4*q+0]);
            acc23[4*q+0] = fma2(w0, x23, acc23[4*q+0]);
            acc01[4*q+1] = fma2(w1, x01, acc01[4*q+1]);
            acc23[4*q+1] = fma2(w1, x23, acc23[4*q+1]);
            acc01[4*q+2] = fma2(w2, x01, acc01[4*q+2]);
            acc23[4*q+2] = fma2(w2, x23, acc23[4*q+2]);
            acc01[4*q+3] = fma2(w3, x01, acc01[4*q+3]);
            acc23[4*q+3] = fma2(w3, x23, acc23[4*q+3]);
        }
    }

    // Unpack + ReLU hidden -> scalar float4 per hidden unit
    float4 hv[D_HID];
#pragma unroll
    for (int d = 0; d < D_HID; d++) {
        float a, b, cc, dd;
        unpack2(acc01[d], a, b);
        unpack2(acc23[d], cc, dd);
        hv[d] = make_float4(fmaxf(a, 0.0f), fmaxf(b, 0.0f),
                            fmaxf(cc, 0.0f), fmaxf(dd, 0.0f));
    }

    // Layer 2 + final relu (max over masked classes == relu of selected head)
    const size_t out_base = (size_t)n * P_OUT * HW + pix;
#pragma unroll
    for (int p = 0; p < P_OUT; p++) {
        float bb = sb2[p];
        float4 o = make_float4(bb, bb, bb, bb);
#pragma unroll
        for (int d = 0; d < D_HID; d++) {
            const float w = sA2[p * D_HID + d];
            o.x = fmaf(w, hv[d].x, o.x);
            o.y = fmaf(w, hv[d].y, o.y);
            o.z = fmaf(w, hv[d].z, o.z);
            o.w = fmaf(w, hv[d].w, o.w);
        }
        o.x = fmaxf(o.x, 0.0f);
        o.y = fmaxf(o.y, 0.0f);
        o.z = fmaxf(o.z, 0.0f);
        o.w = fmaxf(o.w, 0.0f);
        __stcs((float4*)(out + out_base + (size_t)p * HW), o);
    }
}

extern "C" void kernel_launch(void* const* d_in, const int* in_sizes, int n_in,
                              void* d_out, int out_size)
{
    const float* x   = (const float*)d_in[0];
    const int*   cls = (const int*)  d_in[1];
    const float* W1  = (const float*)d_in[2];
    const float* b1  = (const float*)d_in[3];
    const float* g1  = (const float*)d_in[4];
    const float* be1 = (const float*)d_in[5];
    const float* rm1 = (const float*)d_in[6];
    const float* rv1 = (const float*)d_in[7];
    const float* W2  = (const float*)d_in[8];
    const float* b2  = (const float*)d_in[9];
    float* out = (float*)d_out;

    mvpartseg_fused_kernel<<<GRID, THREADS>>>(x, cls, W1, b1, g1, be1, rm1, rv1,
                                              W2, b2, out);
}

// round 16
// speedup vs baseline: 1.0447x; 1.0447x over previous
#include <cuda_runtime.h>
#include <cstdint>

// Problem constants (fixed shapes from reference)
#define NUM_CLASSES 16
#define C_IN 21
#define D_HID 12      // 2*NUM_PARTS
#define P_OUT 7       // NUM_PARTS+1
#define BS 4
#define V 8
#define N_IMG (BS*V)  // 32
#define H 128
#define W 128
#define HW (H*W)      // 16384
#define EPS 1e-5f

#define PIX_PER_THREAD 4
#define THREADS 128
#define PIX_PER_BLOCK (THREADS * PIX_PER_THREAD)        // 512
#define BLOCKS_PER_IMG (HW / PIX_PER_BLOCK)             // 32
#define GRID (N_IMG * BLOCKS_PER_IMG)                   // 1024

#define CH_GROUP 7                                      // channels prefetched per group
#define N_GROUPS (C_IN / CH_GROUP)                      // 3

// Output layout: tuple (out, feats) flattened:
//   out:   (32, 7, 128, 128)  at offset 0
//   feats: (32, 21, 128, 128) after it
#define OUT_ELEMS ((size_t)N_IMG * P_OUT * HW)

typedef unsigned long long u64;

// ---- packed f32x2 helpers (Blackwell FFMA2; ptxas never auto-fuses) ----
__device__ __forceinline__ u64 pack2(float a, float b) {
    u64 r;
    asm("mov.b64 %0, {%1, %2};" : "=l"(r) : "f"(a), "f"(b));
    return r;
}
__device__ __forceinline__ void unpack2(u64 v, float& a, float& b) {
    asm("mov.b64 {%0, %1}, %2;" : "=f"(a), "=f"(b) : "l"(v));
}
__device__ __forceinline__ u64 fma2(u64 a, u64 b, u64 c) {
    u64 d;
    asm("fma.rn.f32x2 %0, %1, %2, %3;" : "=l"(d) : "l"(a), "l"(b), "l"(c));
    return d;
}

__global__ __launch_bounds__(THREADS, 5)   // 102-reg ceiling: room for 7-deep prefetch
void mvpartseg_fused_kernel(const float* __restrict__ x,     // (32,21,128,128)
                            const int*   __restrict__ cls,   // (4,1)
                            const float* __restrict__ W1,    // (16,12,21)
                            const float* __restrict__ b1,    // (16,12)
                            const float* __restrict__ g1,    // (16,12)
                            const float* __restrict__ be1,   // (16,12)
                            const float* __restrict__ rm1,   // (16,12)
                            const float* __restrict__ rv1,   // (16,12)
                            const float* __restrict__ W2,    // (16,7,12)
                            const float* __restrict__ b2,    // (16,7)
                            float* __restrict__ out)
{
    // Layer-1 weights transposed to [c][d]: 12 contiguous floats per channel
    // -> 3x LDS.128 per channel, broadcast (conflict-free).
    __shared__ __align__(16) float sA1t[C_IN * D_HID];   // 252, BN-folded
    __shared__ __align__(16) float sA2[P_OUT * D_HID];   // 84, [p][d]
    __shared__ float sc1[D_HID];                         // BN-folded bias
    __shared__ float sb2[P_OUT];
    __shared__ float sinv[D_HID];

    const int t = threadIdx.x;
    const int n = blockIdx.x / BLOCKS_PER_IMG;       // image (view-folded) index
    const int k = cls[n / V];                        // selected class head

    // Fold BN into conv1 params
    if (t < D_HID) {
        const int i = k * D_HID + t;
        float inv = g1[i] * rsqrtf(rv1[i] + EPS);
        sinv[t] = inv;
        sc1[t]  = b1[i] * inv + be1[i] - rm1[i] * inv;
    }
    if (t < P_OUT) sb2[t] = b2[k * P_OUT + t];
    __syncthreads();

    for (int i = t; i < C_IN * D_HID; i += THREADS) {
        int c = i / D_HID, d = i % D_HID;
        sA1t[i] = W1[k * D_HID * C_IN + d * C_IN + c] * sinv[d];
    }
    for (int i = t; i < P_OUT * D_HID; i += THREADS) {
        sA2[i] = W2[k * P_OUT * D_HID + i];
    }
    __syncthreads();

    const int pix = (blockIdx.x % BLOCKS_PER_IMG) * PIX_PER_BLOCK + t * PIX_PER_THREAD;
    const float* xin  = x + (size_t)n * C_IN * HW + pix;
    float*       fout = out + OUT_ELEMS + (size_t)n * C_IN * HW + pix;

    // Layer-1 accumulators: 4 pixels = 2 packed f32x2 lanes per hidden unit
    u64 acc01[D_HID], acc23[D_HID];
#pragma unroll
    for (int d = 0; d < D_HID; d++) {
        u64 bp = pack2(sc1[d], sc1[d]);
        acc01[d] = bp;
        acc23[d] = bp;
    }

    // Grouped prefetch: force MLP=7 — issue 7 independent LDG.128 back-to-back,
    // THEN drain each with its feats store + packed FFMA2 chain.
#pragma unroll
    for (int g = 0; g < N_GROUPS; g++) {
        float4 xb[CH_GROUP];
#pragma unroll
        for (int j = 0; j < CH_GROUP; j++) {
            const int c = g * CH_GROUP + j;
            xb[j] = *(const float4*)(xin + (size_t)c * HW);
        }
#pragma unroll
        for (int j = 0; j < CH_GROUP; j++) {
            const int c = g * CH_GROUP + j;
            const float4 xv = xb[j];
            __stcs((float4*)(fout + (size_t)c * HW), xv);
            const u64 x01 = pack2(xv.x, xv.y);
            const u64 x23 = pack2(xv.z, xv.w);
            const float4* wrow = (const float4*)&sA1t[c * D_HID];
#pragma unroll
            for (int q = 0; q < D_HID / 4; q++) {
                const float4 w = wrow[q];
                const u64 w0 = pack2(w.x, w.x);
                const u64 w1 = pack2(w.y, w.y);
                const u64 w2 = pack2(w.z, w.z);
                const u64 w3 = pack2(w.w, w.w);
                acc01[4*q+0] = fma2(w0, x01, acc01[4*q+0]);
                acc23[4*q+0] = fma2(w0, x23, acc23[4*q+0]);
                acc01[4*q+1] = fma2(w1, x01, acc01[4*q+1]);
                acc23[4*q+1] = fma2(w1, x23, acc23[4*q+1]);
                acc01[4*q+2] = fma2(w2, x01, acc01[4*q+2]);
                acc23[4*q+2] = fma2(w2, x23, acc23[4*q+2]);
                acc01[4*q+3] = fma2(w3, x01, acc01[4*q+3]);
                acc23[4*q+3] = fma2(w3, x23, acc23[4*q+3]);
            }
        }
    }

    // Unpack + ReLU hidden -> scalar float4 per hidden unit
    float4 hv[D_HID];
#pragma unroll
    for (int d = 0; d < D_HID; d++) {
        float a, b, cc, dd;
        unpack2(acc01[d], a, b);
        unpack2(acc23[d], cc, dd);
        hv[d] = make_float4(fmaxf(a, 0.0f), fmaxf(b, 0.0f),
                            fmaxf(cc, 0.0f), fmaxf(dd, 0.0f));
    }

    // Layer 2 + final relu (max over masked classes == relu of selected head)
    const size_t out_base = (size_t)n * P_OUT * HW + pix;
#pragma unroll
    for (int p = 0; p < P_OUT; p++) {
        float bb = sb2[p];
        float4 o = make_float4(bb, bb, bb, bb);
#pragma unroll
        for (int d = 0; d < D_HID; d++) {
            const float w = sA2[p * D_HID + d];
            o.x = fmaf(w, hv[d].x, o.x);
            o.y = fmaf(w, hv[d].y, o.y);
            o.z = fmaf(w, hv[d].z, o.z);
            o.w = fmaf(w, hv[d].w, o.w);
        }
        o.x = fmaxf(o.x, 0.0f);
        o.y = fmaxf(o.y, 0.0f);
        o.z = fmaxf(o.z, 0.0f);
        o.w = fmaxf(o.w, 0.0f);
        __stcs((float4*)(out + out_base + (size_t)p * HW), o);
    }
}

extern "C" void kernel_launch(void* const* d_in, const int* in_sizes, int n_in,
                              void* d_out, int out_size)
{
    const float* x   = (const float*)d_in[0];
    const int*   cls = (const int*)  d_in[1];
    const float* W1  = (const float*)d_in[2];
    const float* b1  = (const float*)d_in[3];
    const float* g1  = (const float*)d_in[4];
    const float* be1 = (const float*)d_in[5];
    const float* rm1 = (const float*)d_in[6];
    const float* rv1 = (const float*)d_in[7];
    const float* W2  = (const float*)d_in[8];
    const float* b2  = (const float*)d_in[9];
    float* out = (float*)d_out;

    mvpartseg_fused_kernel<<<GRID, THREADS>>>(x, cls, W1, b1, g1, be1, rm1, rv1,
                                              W2, b2, out);
}

// round 17
// speedup vs baseline: 1.0468x; 1.0019x over previous
#include <cuda_runtime.h>
#include <cstdint>

// Problem constants (fixed shapes from reference)
#define NUM_CLASSES 16
#define C_IN 21
#define D_HID 12      // 2*NUM_PARTS
#define P_OUT 7       // NUM_PARTS+1
#define BS 4
#define V 8
#define N_IMG (BS*V)  // 32
#define H 128
#define W 128
#define HW (H*W)      // 16384
#define EPS 1e-5f

#define PIX_PER_THREAD 4
#define THREADS 128
#define PIX_PER_BLOCK (THREADS * PIX_PER_THREAD)        // 512
#define BLOCKS_PER_IMG (HW / PIX_PER_BLOCK)             // 32
#define GRID (N_IMG * BLOCKS_PER_IMG)                   // 1024

#define CH_GROUP 7                                      // channels per pipeline stage
#define N_GROUPS (C_IN / CH_GROUP)                      // 3

// Output layout: tuple (out, feats) flattened:
//   out:   (32, 7, 128, 128)  at offset 0
//   feats: (32, 21, 128, 128) after it
#define OUT_ELEMS ((size_t)N_IMG * P_OUT * HW)

typedef unsigned long long u64;

// ---- packed f32x2 helpers (Blackwell FFMA2; ptxas never auto-fuses) ----
__device__ __forceinline__ u64 pack2(float a, float b) {
    u64 r;
    asm("mov.b64 %0, {%1, %2};" : "=l"(r) : "f"(a), "f"(b));
    return r;
}
__device__ __forceinline__ void unpack2(u64 v, float& a, float& b) {
    asm("mov.b64 {%0, %1}, %2;" : "=f"(a), "=f"(b) : "l"(v));
}
__device__ __forceinline__ u64 fma2(u64 a, u64 b, u64 c) {
    u64 d;
    asm("fma.rn.f32x2 %0, %1, %2, %3;" : "=l"(d) : "l"(a), "l"(b), "l"(c));
    return d;
}

__global__ __launch_bounds__(THREADS, 4)   // 128-reg ceiling: 2-deep group pipeline
void mvpartseg_fused_kernel(const float* __restrict__ x,     // (32,21,128,128)
                            const int*   __restrict__ cls,   // (4,1)
                            const float* __restrict__ W1,    // (16,12,21)
                            const float* __restrict__ b1,    // (16,12)
                            const float* __restrict__ g1,    // (16,12)
                            const float* __restrict__ be1,   // (16,12)
                            const float* __restrict__ rm1,   // (16,12)
                            const float* __restrict__ rv1,   // (16,12)
                            const float* __restrict__ W2,    // (16,7,12)
                            const float* __restrict__ b2,    // (16,7)
                            float* __restrict__ out)
{
    // Layer-1 weights transposed to [c][d]: 12 contiguous floats per channel
    // -> 3x LDS.128 per channel, broadcast (conflict-free).
    __shared__ __align__(16) float sA1t[C_IN * D_HID];   // 252, BN-folded
    __shared__ __align__(16) float sA2[P_OUT * D_HID];   // 84, [p][d]
    __shared__ float sc1[D_HID];                         // BN-folded bias
    __shared__ float sb2[P_OUT];
    __shared__ float sinv[D_HID];

    const int t = threadIdx.x;
    const int n = blockIdx.x / BLOCKS_PER_IMG;       // image (view-folded) index
    const int k = cls[n / V];                        // selected class head

    // Fold BN into conv1 params
    if (t < D_HID) {
        const int i = k * D_HID + t;
        float inv = g1[i] * rsqrtf(rv1[i] + EPS);
        sinv[t] = inv;
        sc1[t]  = b1[i] * inv + be1[i] - rm1[i] * inv;
    }
    if (t < P_OUT) sb2[t] = b2[k * P_OUT + t];
    __syncthreads();

    for (int i = t; i < C_IN * D_HID; i += THREADS) {
        int c = i / D_HID, d = i % D_HID;
        sA1t[i] = W1[k * D_HID * C_IN + d * C_IN + c] * sinv[d];
    }
    for (int i = t; i < P_OUT * D_HID; i += THREADS) {
        sA2[i] = W2[k * P_OUT * D_HID + i];
    }
    __syncthreads();

    const int pix = (blockIdx.x % BLOCKS_PER_IMG) * PIX_PER_BLOCK + t * PIX_PER_THREAD;
    const float* xin  = x + (size_t)n * C_IN * HW + pix;
    float*       fout = out + OUT_ELEMS + (size_t)n * C_IN * HW + pix;

    // Layer-1 accumulators: 4 pixels = 2 packed f32x2 lanes per hidden unit
    u64 acc01[D_HID], acc23[D_HID];
#pragma unroll
    for (int d = 0; d < D_HID; d++) {
        u64 bp = pack2(sc1[d], sc1[d]);
        acc01[d] = bp;
        acc23[d] = bp;
    }

    // Software-pipelined groups: loads for group g+1 are issued BEFORE the
    // drain of group g, keeping ~7 LDG.128 in flight continuously.
    float4 buf[2][CH_GROUP];

    // Prologue: prefetch group 0
#pragma unroll
    for (int j = 0; j < CH_GROUP; j++) {
        buf[0][j] = *(const float4*)(xin + (size_t)j * HW);
    }

#pragma unroll
    for (int g = 0; g < N_GROUPS; g++) {
        const int cur = g & 1;
        // Prefetch next group first (independent of the drain below).
        if (g + 1 < N_GROUPS) {
#pragma unroll
            for (int j = 0; j < CH_GROUP; j++) {
                const int c = (g + 1) * CH_GROUP + j;
                buf[cur ^ 1][j] = *(const float4*)(xin + (size_t)c * HW);
            }
        }
        // Drain current group: feats store + packed FFMA2 chain per channel.
#pragma unroll
        for (int j = 0; j < CH_GROUP; j++) {
            const int c = g * CH_GROUP + j;
            const float4 xv = buf[cur][j];
            __stcs((float4*)(fout + (size_t)c * HW), xv);
            const u64 x01 = pack2(xv.x, xv.y);
            const u64 x23 = pack2(xv.z, xv.w);
            const float4* wrow = (const float4*)&sA1t[c * D_HID];
#pragma unroll
            for (int q = 0; q < D_HID / 4; q++) {
                const float4 w = wrow[q];
                const u64 w0 = pack2(w.x, w.x);
                const u64 w1 = pack2(w.y, w.y);
                const u64 w2 = pack2(w.z, w.z);
                const u64 w3 = pack2(w.w, w.w);
                acc01[4*q+0] = fma2(w0, x01, acc01[4*q+0]);
                acc23[4*q+0] = fma2(w0, x23, acc23[4*q+0]);
                acc01[4*q+1] = fma2(w1, x01, acc01[4*q+1]);
                acc23[4*q+1] = fma2(w1, x23, acc23[4*q+1]);
                acc01[4*q+2] = fma2(w2, x01, acc01[4*q+2]);
                acc23[4*q+2] = fma2(w2, x23, acc23[4*q+2]);
                acc01[4*q+3] = fma2(w3, x01, acc01[4*q+3]);
                acc23[4*q+3] = fma2(w3, x23, acc23[4*q+3]);
            }
        }
    }

    // Unpack + ReLU hidden -> scalar float4 per hidden unit
    float4 hv[D_HID];
#pragma unroll
    for (int d = 0; d < D_HID; d++) {
        float a, b, cc, dd;
        unpack2(acc01[d], a, b);
        unpack2(acc23[d], cc, dd);
        hv[d] = make_float4(fmaxf(a, 0.0f), fmaxf(b, 0.0f),
                            fmaxf(cc, 0.0f), fmaxf(dd, 0.0f));
    }

    // Layer 2 + final relu (max over masked classes == relu of selected head)
    const size_t out_base = (size_t)n * P_OUT * HW + pix;
#pragma unroll
    for (int p = 0; p < P_OUT; p++) {
        float bb = sb2[p];
        float4 o = make_float4(bb, bb, bb, bb);
#pragma unroll
        for (int d = 0; d < D_HID; d++) {
            const float w = sA2[p * D_HID + d];
            o.x = fmaf(w, hv[d].x, o.x);
            o.y = fmaf(w, hv[d].y, o.y);
            o.z = fmaf(w, hv[d].z, o.z);
            o.w = fmaf(w, hv[d].w, o.w);
        }
        o.x = fmaxf(o.x, 0.0f);
        o.y = fmaxf(o.y, 0.0f);
        o.z = fmaxf(o.z, 0.0f);
        o.w = fmaxf(o.w, 0.0f);
        __stcs((float4*)(out + out_base + (size_t)p * HW), o);
    }
}

extern "C" void kernel_launch(void* const* d_in, const int* in_sizes, int n_in,
                              void* d_out, int out_size)
{
    const float* x   = (const float*)d_in[0];
    const int*   cls = (const int*)  d_in[1];
    const float* W1  = (const float*)d_in[2];
    const float* b1  = (const float*)d_in[3];
    const float* g1  = (const float*)d_in[4];
    const float* be1 = (const float*)d_in[5];
    const float* rm1 = (const float*)d_in[6];
    const float* rv1 = (const float*)d_in[7];
    const float* W2  = (const float*)d_in[8];
    const float* b2  = (const float*)d_in[9];
    float* out = (float*)d_out;

    mvpartseg_fused_kernel<<<GRID, THREADS>>>(x, cls, W1, b1, g1, be1, rm1, rv1,
                                              W2, b2, out);
}